// round 10
// baseline (speedup 1.0000x reference)
#include <cuda_runtime.h>
#include <math.h>

#define S_LEN  1024
#define B_SIZE 512
#define NTAG   48
#define PF     4
#define TMID   511
#define NCHUNK 64
#define CHUNK  (S_LEN / NCHUNK)

__device__ float g_fa[B_SIZE][64];    // alpha at t=TMID (unnormalized)
__device__ float g_bu[B_SIZE][64];    // beta-u at t=TMID (unnormalized)
__device__ float g_Mf[B_SIZE];
__device__ float g_Mb[B_SIZE];
__device__ float g_pnum[NCHUNK][B_SIZE];
__device__ int   g_pcnt[NCHUNK][B_SIZE];

// ---- one CTA (64 threads, 2 warps) = one half-chain.
// blocks 0..511: forward t=1..511 ; blocks 512..1023: backward t=1023..512.
// Step body is the proven R6 structure: double-buffered shared state,
// float4 reads, scalar FFMA, exactly one __syncthreads per step.
__global__ void __launch_bounds__(64)
crf_fwdbwd_kernel(const float* __restrict__ emissions,
                  const int* __restrict__ mask,
                  const float* __restrict__ start_t,
                  const float* __restrict__ end_t,
                  const float* __restrict__ trans)
{
    const int dir  = blockIdx.x >> 9;
    const int b    = blockIdx.x & (B_SIZE - 1);
    const int j    = threadIdx.x;       // 0..63, tags 0..47
    const int lane = j & 31;
    const int wid  = j >> 5;
    const bool act = (j < NTAG);

    __shared__ __align__(16) float v_sh[2][64];
    __shared__ float wred[2];
    __shared__ float red[2];

    // E[k]: fwd -> exp(T[k][j]) (column j), bwd -> exp(T[j][k]) (row j)
    float E[NTAG];
#pragma unroll
    for (int k = 0; k < NTAG; k++)
        E[k] = act ? __expf(dir == 0 ? trans[k * NTAG + j] : trans[j * NTAG + k]) : 0.f;

    float M = 0.f;
    int nupd = 0;
    float w;                 // fwd: alpha_j ; bwd: u_j
    float pf[PF];
    unsigned mbits;

    if (dir == 0) {
        // ---- forward init (t = 0) ----
        float em0 = act ? emissions[(size_t)b * NTAG + j] : 0.f;
        w = act ? __expf(start_t[j] + em0) : 0.f;
        v_sh[0][j] = w;
        v_sh[1][j] = 0.f;
#pragma unroll
        for (int k = 0; k < PF; k++) {
            int t = 1 + k;
            pf[t & (PF - 1)] = act ? emissions[((size_t)t * B_SIZE + b) * NTAG + j] : 0.f;
        }
        {
            int mt = mask[(size_t)lane * B_SIZE + b];
            mbits = __ballot_sync(0xffffffffu, mt != 0);
        }
        int cur = 0;
        __syncthreads();

        for (int t = 1; t <= TMID; t++) {
            if ((t & 31) == 0) {
                int mt = mask[(size_t)(t + lane) * B_SIZE + b];
                mbits = __ballot_sync(0xffffffffu, mt != 0);
            }
            const int m_t = (mbits >> (t & 31)) & 1;

            const int slot = t & (PF - 1);
            const float e_em = __expf(pf[slot]);
            int tn = t + PF; if (tn > TMID) tn = TMID;
            pf[slot] = act ? emissions[((size_t)tn * B_SIZE + b) * NTAG + j] : 0.f;

            const float* vv = v_sh[cur];
            float s0 = 0.f, s1 = 0.f, s2 = 0.f, s3 = 0.f;
#pragma unroll
            for (int i = 0; i < NTAG; i += 4) {
                const float4 v4 = *(const float4*)(vv + i);
                s0 = fmaf(v4.x, E[i + 0], s0);
                s1 = fmaf(v4.y, E[i + 1], s1);
                s2 = fmaf(v4.z, E[i + 2], s2);
                s3 = fmaf(v4.w, E[i + 3], s3);
            }
            float nw = ((s0 + s1) + (s2 + s3)) * e_em;

            if (m_t) {
                w = nw;
                if (((++nupd) & 7) == 0) {
                    float r = w;
#pragma unroll
                    for (int o = 16; o > 0; o >>= 1)
                        r = fmaxf(r, __shfl_xor_sync(0xffffffffu, r, o));
                    if (lane == 0) wred[wid] = r;
                    __syncthreads();
                    r = fmaxf(fmaxf(wred[0], wred[1]), 1e-30f);
                    M += __logf(r);
                    w *= (1.f / r);
                }
            }
            v_sh[cur ^ 1][j] = w;      // store (possibly unchanged) state
            __syncthreads();
            cur ^= 1;
        }
        g_fa[b][j] = w;
        if (j == 0) g_Mf[b] = M;
    } else {
        // ---- backward init (t = 1023): u = exp(end), z = u * exp(em[1023]) ----
        float em0 = act ? emissions[((size_t)(S_LEN - 1) * B_SIZE + b) * NTAG + j] : 0.f;
        w = act ? __expf(end_t[j]) : 0.f;
        v_sh[0][j] = w * __expf(em0);   // z_1023
        v_sh[1][j] = 0.f;
#pragma unroll
        for (int k = 0; k < PF; k++) {
            int t = 1022 - k;           // em needed at tt-1 for tt = 1023..1020
            pf[t & (PF - 1)] = act ? emissions[((size_t)t * B_SIZE + b) * NTAG + j] : 0.f;
        }
        {
            int mt = mask[(size_t)(992 + lane) * B_SIZE + b];   // chunk [992..1023]
            mbits = __ballot_sync(0xffffffffu, mt != 0);
        }
        int cur = 0;
        __syncthreads();

        for (int tt = S_LEN - 1; tt > TMID; tt--) {
            // mask chunk containing tt already loaded; reload when crossing down
            const int m_t = (mbits >> (tt & 31)) & 1;   // mask[tt]

            const int tm1 = tt - 1;
            const int slot = tm1 & (PF - 1);
            const float e_em = __expf(pf[slot]);        // exp(em[tt-1])
            int tn = tm1 - PF; if (tn < TMID) tn = TMID;
            pf[slot] = act ? emissions[((size_t)tn * B_SIZE + b) * NTAG + j] : 0.f;

            if (m_t) {
                const float* vv = v_sh[cur];
                float s0 = 0.f, s1 = 0.f, s2 = 0.f, s3 = 0.f;
#pragma unroll
                for (int k = 0; k < NTAG; k += 4) {
                    const float4 v4 = *(const float4*)(vv + k);
                    s0 = fmaf(v4.x, E[k + 0], s0);
                    s1 = fmaf(v4.y, E[k + 1], s1);
                    s2 = fmaf(v4.z, E[k + 2], s2);
                    s3 = fmaf(v4.w, E[k + 3], s3);
                }
                w = (s0 + s1) + (s2 + s3);
                if (((++nupd) & 7) == 0) {
                    float r = w;
#pragma unroll
                    for (int o = 16; o > 0; o >>= 1)
                        r = fmaxf(r, __shfl_xor_sync(0xffffffffu, r, o));
                    if (lane == 0) wred[wid] = r;
                    __syncthreads();
                    r = fmaxf(fmaxf(wred[0], wred[1]), 1e-30f);
                    M += __logf(r);
                    w *= (1.f / r);
                }
            }
            // z_{tt-1} = u_{tt-1} * exp(em[tt-1]); always refresh from registers
            v_sh[cur ^ 1][j] = w * e_em;
            __syncthreads();
            cur ^= 1;
            if (((tt - 1) & 31) == 31) {          // next iter enters lower chunk
                int base = tt - 32;               // = (tt-1) - 31
                int mt = mask[(size_t)(base + lane) * B_SIZE + b];
                mbits = __ballot_sync(0xffffffffu, mt != 0);
            }
        }
        g_bu[b][j] = w;                           // u at t = TMID
        if (j == 0) g_Mb[b] = M;
    }
}

// ---- numerator partials: coalesced over batch, 64-way parallel over t ----
__global__ void __launch_bounds__(B_SIZE)
crf_num_kernel(const float* __restrict__ emissions,
               const int* __restrict__ tags,
               const int* __restrict__ mask,
               const float* __restrict__ start_t,
               const float* __restrict__ trans)
{
    const int b  = threadIdx.x;
    const int c  = blockIdx.x;
    const int t0 = c * CHUNK;

    float acc = 0.f;
    int cnt = 0;
    int tp = (t0 > 0) ? tags[(t0 - 1) * B_SIZE + b] : 0;
#pragma unroll
    for (int k = 0; k < CHUNK; k++) {
        int t  = t0 + k;
        int tg = tags[t * B_SIZE + b];
        int m  = mask[t * B_SIZE + b];
        cnt += m;
        if (t == 0) {
            acc += start_t[tg] + emissions[(size_t)b * NTAG + tg];
        } else {
            acc += (trans[tp * NTAG + tg] +
                    emissions[((size_t)t * B_SIZE + b) * NTAG + tg]) * (float)m;
        }
        tp = tg;
    }
    g_pnum[c][b] = acc;
    g_pcnt[c][b] = cnt;
}

// ---- final: end-term + alpha.beta dot + mean ----
__global__ void __launch_bounds__(B_SIZE)
crf_reduce_kernel(float* __restrict__ out,
                  const int* __restrict__ tags,
                  const float* __restrict__ end_t)
{
    __shared__ float sh[B_SIZE];
    const int b = threadIdx.x;

    float num = 0.f;
    int cnt = 0;
#pragma unroll
    for (int c = 0; c < NCHUNK; c++) { num += g_pnum[c][b]; cnt += g_pcnt[c][b]; }
    num += end_t[tags[(cnt - 1) * B_SIZE + b]];

    float dot = 0.f;
    const float4* fa = (const float4*)g_fa[b];
    const float4* bu = (const float4*)g_bu[b];
#pragma unroll
    for (int k = 0; k < 12; k++) {     // 48 floats
        float4 x = fa[k], y = bu[k];
        dot += x.x * y.x + x.y * y.y + x.z * y.z + x.w * y.w;
    }
    const float den = g_Mf[b] + g_Mb[b] + __logf(dot);

    sh[b] = num - den;
    __syncthreads();
#pragma unroll
    for (int o = B_SIZE / 2; o > 0; o >>= 1) {
        if (b < o) sh[b] += sh[b + o];
        __syncthreads();
    }
    if (b == 0) out[0] = sh[0] * (1.f / (float)B_SIZE);
}

extern "C" void kernel_launch(void* const* d_in, const int* in_sizes, int n_in,
                              void* d_out, int out_size)
{
    const float* emissions = (const float*)d_in[0];
    const int*   tags      = (const int*)d_in[1];
    const int*   mask      = (const int*)d_in[2];
    const float* start_t   = (const float*)d_in[3];
    const float* end_t     = (const float*)d_in[4];
    const float* trans     = (const float*)d_in[5];

    crf_fwdbwd_kernel<<<2 * B_SIZE, 64>>>(emissions, mask, start_t, end_t, trans);
    crf_num_kernel<<<NCHUNK, B_SIZE>>>(emissions, tags, mask, start_t, trans);
    crf_reduce_kernel<<<1, B_SIZE>>>((float*)d_out, tags, end_t);
}